// round 13
// baseline (speedup 1.0000x reference)
#include <cuda_runtime.h>
#include <math.h>
#include <cstdint>

// Problem constants
#define Bb   4
#define Ss   1024
#define Dd   1024
#define DIi  4096
#define Mm   (Bb*Ss)      // 4096 rows

// ---------------- scratch (device globals; no allocations allowed) ----------
__device__ float g_qkv[(size_t)Mm * 3 * Dd];          // 4096 x 3072
__device__ float g_attn_in[(size_t)Mm * Dd];
__device__ float g_attn_out[(size_t)Mm * Dd];
__device__ float g_out1[(size_t)Mm * Dd];
__device__ float g_core[(size_t)Mm * DIi];
__device__ float g_core2[(size_t)Mm * Dd];
__device__ unsigned char g_maskc[Mm];

// ---------------- helpers ---------------------------------------------------
__device__ __forceinline__ uint32_t smem_u32(const void* p) {
    uint32_t a;
    asm("{ .reg .u64 t; cvta.to.shared.u64 t, %1; cvt.u32.u64 %0, t; }"
        : "=r"(a) : "l"(p));
    return a;
}
__device__ __forceinline__ void cp16(uint32_t dst, const void* src, int sz) {
    asm volatile("cp.async.ca.shared.global [%0], [%1], 16, %2;"
                 :: "r"(dst), "l"(src), "r"(sz));
}
__device__ __forceinline__ uint32_t f2tf(float x) {
    uint32_t r;
    asm("cvt.rna.tf32.f32 %0, %1;" : "=r"(r) : "f"(x));
    return r;
}
__device__ __forceinline__ void mma_tf32(float* c, const uint32_t* a, const uint32_t* b) {
    asm volatile(
        "mma.sync.aligned.m16n8k8.row.col.f32.tf32.tf32.f32 "
        "{%0,%1,%2,%3}, {%4,%5,%6,%7}, {%8,%9}, {%0,%1,%2,%3};"
        : "+f"(c[0]), "+f"(c[1]), "+f"(c[2]), "+f"(c[3])
        : "r"(a[0]), "r"(a[1]), "r"(a[2]), "r"(a[3]), "r"(b[0]), "r"(b[1]));
}

// ======================= mma.sync tf32 GEMM =================================
// 256 threads, 2x4 warp grid, warp tile 64x64, raw fp32->tf32 (HW truncation).
// R12: 3-stage cp.async pipeline, ONE __syncthreads per chunk.
//   Invariant: top-of-iter sync proves compute(c-1) done in all warps, so
//   buffer (c-1)%3 == (c+2)%3 is free for load(c+2) issued right after sync.
// C[128x256] = A[128xK] @ W[K,N] row-major, fp32 accum, BK=32.
// convCin>0: A is im2col of X[B,S,Cin], ksize 3, SAME padding.
#define SA_  36
#define SB_  264            // 256 + 8
#define STG_A (128 * SA_)
#define STG_B (32 * SB_)
#define SMEM_G256 (3 * (STG_A + STG_B) * 4)   // 156672

__global__ __launch_bounds__(256) void gemm_mma(
    const float* __restrict__ A, const float* __restrict__ Bw,
    const float* __restrict__ bias, float* __restrict__ C,
    int K, int lda, int ldb, int ldc, int convCin, int relu)
{
    extern __shared__ float sm[];
    int tid = threadIdx.x;
    int m0 = blockIdx.y * 128, bn = blockIdx.x * 256;

    int NC = K >> 5;

    auto load_chunk = [&](int c, int stage) {
        int k0 = c << 5;
        float* sa = sm + stage * (STG_A + STG_B);
        float* sb = sa + STG_A;
        if (convCin) {
            int t = k0 / convCin, cb2 = k0 - t * convCin;
#pragma unroll
            for (int i = 0; i < 4; i++) {
                int idx = tid + i * 256;          // 0..1023
                int row = idx >> 3, c4 = idx & 7;
                int m = m0 + row, b_ = m >> 10, s_ = m & 1023, ss = s_ + t - 1;
                const float* src = A + (size_t)(b_ * Ss + ss) * convCin + cb2 + c4 * 4;
                cp16(smem_u32(sa + row * SA_ + c4 * 4), src,
                     (ss >= 0 && ss < Ss) ? 16 : 0);
            }
        } else {
#pragma unroll
            for (int i = 0; i < 4; i++) {
                int idx = tid + i * 256;
                int row = idx >> 3, c4 = idx & 7;
                cp16(smem_u32(sa + row * SA_ + c4 * 4),
                     A + (size_t)(m0 + row) * lda + k0 + c4 * 4, 16);
            }
        }
#pragma unroll
        for (int i = 0; i < 8; i++) {
            int idx = tid + i * 256;              // 0..2047
            int kk = idx >> 6, n4 = idx & 63;
            cp16(smem_u32(sb + kk * SB_ + n4 * 4),
                 Bw + (size_t)(k0 + kk) * ldb + bn + n4 * 4, 16);
        }
        asm volatile("cp.async.commit_group;");
    };

    int w = tid >> 5, lane = tid & 31;
    int wr = w & 1, wc = w >> 1;      // 2x4 warp grid; warp tile 64x64
    int grp = lane >> 2, tg = lane & 3;

    float acc[4][8][4];
#pragma unroll
    for (int mi = 0; mi < 4; mi++)
#pragma unroll
        for (int nj = 0; nj < 8; nj++)
#pragma unroll
            for (int q = 0; q < 4; q++) acc[mi][nj][q] = 0.f;

    int stage = 0;                     // c % 3 without modulo
    load_chunk(0, 0);
    if (NC > 1) load_chunk(1, 1);
    for (int c = 0; c < NC; c++) {
        if (c + 1 < NC) asm volatile("cp.async.wait_group 1;");
        else            asm volatile("cp.async.wait_group 0;");
        __syncthreads();
        // issue loads for c+2 into the buffer freed by compute(c-1)
        if (c + 2 < NC) {
            int ls = stage + 2; if (ls >= 3) ls -= 3;
            load_chunk(c + 2, ls);
        }
        const uint32_t* sa = (const uint32_t*)(sm + stage * (STG_A + STG_B));
        const uint32_t* sb = sa + STG_A;
#pragma unroll
        for (int ks = 0; ks < 4; ks++) {
            int kb = ks * 8;
            uint32_t afr[4][4];
#pragma unroll
            for (int mi = 0; mi < 4; mi++) {
                const uint32_t* ab = sa + (wr * 64 + mi * 16) * SA_ + kb;
                afr[mi][0] = ab[grp * SA_ + tg];
                afr[mi][1] = ab[(grp + 8) * SA_ + tg];
                afr[mi][2] = ab[grp * SA_ + tg + 4];
                afr[mi][3] = ab[(grp + 8) * SA_ + tg + 4];
            }
            uint32_t bfr[8][2];
#pragma unroll
            for (int nj = 0; nj < 8; nj++) {
                int ncol = wc * 64 + nj * 8 + grp;
                bfr[nj][0] = sb[(kb + tg) * SB_ + ncol];
                bfr[nj][1] = sb[(kb + tg + 4) * SB_ + ncol];
            }
#pragma unroll
            for (int mi = 0; mi < 4; mi++)
#pragma unroll
                for (int nj = 0; nj < 8; nj++)
                    mma_tf32(acc[mi][nj], afr[mi], bfr[nj]);
        }
        if (++stage >= 3) stage -= 3;
    }

#pragma unroll
    for (int mi = 0; mi < 4; mi++) {
        int r0 = m0 + wr * 64 + mi * 16 + grp;
#pragma unroll
        for (int nj = 0; nj < 8; nj++) {
            int c0 = bn + wc * 64 + nj * 8 + tg * 2;
            float v0 = acc[mi][nj][0], v1 = acc[mi][nj][1];
            float v2 = acc[mi][nj][2], v3 = acc[mi][nj][3];
            if (bias) {
                float b0 = bias[c0], b1 = bias[c0 + 1];
                v0 += b0; v1 += b1; v2 += b0; v3 += b1;
            }
            if (relu) {
                v0 = fmaxf(v0, 0.f); v1 = fmaxf(v1, 0.f);
                v2 = fmaxf(v2, 0.f); v3 = fmaxf(v3, 0.f);
            }
            *(float2*)&C[(size_t)r0 * ldc + c0] = make_float2(v0, v1);
            *(float2*)&C[(size_t)(r0 + 8) * ldc + c0] = make_float2(v2, v3);
        }
    }
}

// ======================= fused flash attention ==============================
// One block = (r = b*16+h, 128 q-rows). Loops over 8 key-tiles of 128.
// S = Q@K^T (tf32 mma), faithful mask (valid -> -1e30, pad -> s*0.125+1),
// online softmax (max/sum with cross-warp-pair exchange), O = P@V (tf32 mma).
// Output scramble: attn_in[bo= r%B][q][ (ho=r/B)*64 + d ].
#define FL_SK 68
#define FL_SV 72
#define FL_SP 132
#define SMEM_FLASH ((2*128*FL_SK + 2*128*FL_SV + 128*FL_SP) * 4)  // 210944

__global__ __launch_bounds__(256) void flash_k(const float* __restrict__ qkvp)
{
    extern __shared__ float sm[];
    float* Ks = sm;                               // 2 stages
    float* Vs = sm + 2 * 128 * FL_SK;             // 2 stages
    float* Ps = sm + 2 * 128 * FL_SK + 2 * 128 * FL_SV;  // P tile (also Q staging)
    __shared__ float s_red[2][128];
    __shared__ float s_mask[128];

    int tid = threadIdx.x;
    int r = blockIdx.y, m0 = blockIdx.x * 128;
    int bb = r >> 4, h = r & 15, mb = r & 3;
    const float* Qb = qkvp + (size_t)(bb * Ss) * 3072 + h * 64;
    const float* Kb = Qb + 1024;
    const float* Vb = Qb + 2048;

    int w = tid >> 5, lane = tid & 31;
    int wr = w & 3, wc = w >> 2;      // 4x2: warp = 32 q-rows x (64 keys | 32 dims)
    int grp = lane >> 2, tg = lane & 3;
    int rowbase = wr * 32;

    auto load_pair = [&](int t) {
        float* kd = Ks + (t & 1) * 128 * FL_SK;
        float* vd = Vs + (t & 1) * 128 * FL_SV;
        int j0 = t * 128;
#pragma unroll
        for (int i = 0; i < 8; i++) {
            int idx = tid + i * 256;              // 0..2047
            int row = idx >> 4, c4 = idx & 15;
            cp16(smem_u32(kd + row * FL_SK + c4 * 4),
                 Kb + (size_t)(j0 + row) * 3072 + c4 * 4, 16);
            cp16(smem_u32(vd + row * FL_SV + c4 * 4),
                 Vb + (size_t)(j0 + row) * 3072 + c4 * 4, 16);
        }
        asm volatile("cp.async.commit_group;");
    };
    load_pair(0);
    load_pair(1);

    // stage Q (128x64) into Ps area (stride FL_SK), then lift to registers
#pragma unroll
    for (int i = 0; i < 8; i++) {
        int idx = tid + i * 256;                  // float4 id 0..2047
        int row = idx >> 4, c4 = idx & 15;
        *(float4*)(Ps + row * FL_SK + c4 * 4) =
            *(const float4*)(Qb + (size_t)(m0 + row) * 3072 + c4 * 4);
    }
    __syncthreads();
    uint32_t qfr[2][8][4];
#pragma unroll
    for (int mi = 0; mi < 2; mi++) {
        const float* ab = Ps + (rowbase + mi * 16) * FL_SK;
#pragma unroll
        for (int ks = 0; ks < 8; ks++) {
            int kb = ks * 8;
            qfr[mi][ks][0] = f2tf(ab[grp * FL_SK + kb + tg]);
            qfr[mi][ks][1] = f2tf(ab[(grp + 8) * FL_SK + kb + tg]);
            qfr[mi][ks][2] = f2tf(ab[grp * FL_SK + kb + tg + 4]);
            qfr[mi][ks][3] = f2tf(ab[(grp + 8) * FL_SK + kb + tg + 4]);
        }
    }

    float o[2][4][4];
    float m_run[2][2], s_run[2][2];
#pragma unroll
    for (int mi = 0; mi < 2; mi++) {
        m_run[mi][0] = -INFINITY; m_run[mi][1] = -INFINITY;
        s_run[mi][0] = 0.f;       s_run[mi][1] = 0.f;
#pragma unroll
        for (int nj = 0; nj < 4; nj++)
#pragma unroll
            for (int q = 0; q < 4; q++) o[mi][nj][q] = 0.f;
    }

    for (int t = 0; t < 8; t++) {
        if (tid < 128)
            s_mask[tid] = g_maskc[mb * Ss + t * 128 + tid] ? 1.f : 0.f;
        if (t < 7) asm volatile("cp.async.wait_group 1;");
        else       asm volatile("cp.async.wait_group 0;");
        __syncthreads();
        const float* kt_s = Ks + (t & 1) * 128 * FL_SK;
        const float* vt_s = Vs + (t & 1) * 128 * FL_SV;

        // ---- S = Q @ K^T : warp computes 32 x 64 ----
        float s[2][8][4];
#pragma unroll
        for (int mi = 0; mi < 2; mi++)
#pragma unroll
            for (int nj = 0; nj < 8; nj++)
#pragma unroll
                for (int q = 0; q < 4; q++) s[mi][nj][q] = 0.f;
#pragma unroll
        for (int ks = 0; ks < 8; ks++) {
            int kb = ks * 8;
            uint32_t bfr[8][2];
#pragma unroll
            for (int nj = 0; nj < 8; nj++) {
                int ncol = wc * 64 + nj * 8 + grp;
                bfr[nj][0] = f2tf(kt_s[ncol * FL_SK + kb + tg]);
                bfr[nj][1] = f2tf(kt_s[ncol * FL_SK + kb + tg + 4]);
            }
#pragma unroll
            for (int mi = 0; mi < 2; mi++)
#pragma unroll
                for (int nj = 0; nj < 8; nj++)
                    mma_tf32(s[mi][nj], qfr[mi][ks], bfr[nj]);
        }

        // ---- faithful mask transform + tile row max ----
        float tmax[2][2];
        tmax[0][0] = tmax[0][1] = tmax[1][0] = tmax[1][1] = -INFINITY;
#pragma unroll
        for (int mi = 0; mi < 2; mi++)
#pragma unroll
            for (int nj = 0; nj < 8; nj++) {
                float mk0 = s_mask[wc * 64 + nj * 8 + tg * 2];
                float mk1 = s_mask[wc * 64 + nj * 8 + tg * 2 + 1];
                float v0 = (mk0 != 0.f) ? -1e30f : (s[mi][nj][0] * 0.125f + 1.0f);
                float v1 = (mk1 != 0.f) ? -1e30f : (s[mi][nj][1] * 0.125f + 1.0f);
                float v2 = (mk0 != 0.f) ? -1e30f : (s[mi][nj][2] * 0.125f + 1.0f);
                float v3 = (mk1 != 0.f) ? -1e30f : (s[mi][nj][3] * 0.125f + 1.0f);
                s[mi][nj][0] = v0; s[mi][nj][1] = v1;
                s[mi][nj][2] = v2; s[mi][nj][3] = v3;
                tmax[mi][0] = fmaxf(tmax[mi][0], fmaxf(v0, v1));
                tmax[mi][1] = fmaxf(tmax[mi][1], fmaxf(v2, v3));
            }
#pragma unroll
        for (int mi = 0; mi < 2; mi++)
#pragma unroll
            for (int hh = 0; hh < 2; hh++) {
                float v = tmax[mi][hh];
                v = fmaxf(v, __shfl_xor_sync(0xffffffffu, v, 1));
                v = fmaxf(v, __shfl_xor_sync(0xffffffffu, v, 2));
                tmax[mi][hh] = v;
                s_red[wc][rowbase + mi * 16 + grp + hh * 8] = v;
            }
        __syncthreads();

        float mnew[2][2];
#pragma unroll
        for (int mi = 0; mi < 2; mi++)
#pragma unroll
            for (int hh = 0; hh < 2; hh++) {
                float other = s_red[wc ^ 1][rowbase + mi * 16 + grp + hh * 8];
                float mn = fmaxf(m_run[mi][hh], fmaxf(tmax[mi][hh], other));
                float sc = __expf(m_run[mi][hh] - mn);
                s_run[mi][hh] *= sc;
                m_run[mi][hh] = mn;
                mnew[mi][hh] = mn;
#pragma unroll
                for (int nj = 0; nj < 4; nj++) {
                    o[mi][nj][hh * 2]     *= sc;
                    o[mi][nj][hh * 2 + 1] *= sc;
                }
            }

        // ---- P = exp(S - m), partial row sums, stage P to SMEM ----
#pragma unroll
        for (int mi = 0; mi < 2; mi++) {
            float ps0 = 0.f, ps1 = 0.f;
#pragma unroll
            for (int nj = 0; nj < 8; nj++) {
                float p0 = __expf(s[mi][nj][0] - mnew[mi][0]);
                float p1 = __expf(s[mi][nj][1] - mnew[mi][0]);
                float p2 = __expf(s[mi][nj][2] - mnew[mi][1]);
                float p3 = __expf(s[mi][nj][3] - mnew[mi][1]);
                ps0 += p0 + p1; ps1 += p2 + p3;
                int row = rowbase + mi * 16 + grp;
                int col = wc * 64 + nj * 8 + tg * 2;
                *(float2*)(Ps + row * FL_SP + col)       = make_float2(p0, p1);
                *(float2*)(Ps + (row + 8) * FL_SP + col) = make_float2(p2, p3);
            }
            s_run[mi][0] += ps0; s_run[mi][1] += ps1;
        }
        __syncthreads();

        // ---- O += P @ V : warp computes 32 x 32, k = 128 ----
#pragma unroll
        for (int ks2 = 0; ks2 < 16; ks2++) {
            int kb = ks2 * 8;
            uint32_t afr2[2][4];
#pragma unroll
            for (int mi = 0; mi < 2; mi++) {
                const float* ab = Ps + (rowbase + mi * 16) * FL_SP + kb;
                afr2[mi][0] = f2tf(ab[grp * FL_SP + tg]);
                afr2[mi][1] = f2tf(ab[(grp + 8) * FL_SP + tg]);
                afr2[mi][2] = f2tf(ab[grp * FL_SP + tg + 4]);
                afr2[mi][3] = f2tf(ab[(grp + 8) * FL_SP + tg + 4]);
            }
            uint32_t bfr2[4][2];
#pragma unroll
            for (int nj = 0; nj < 4; nj++) {
                int ncol = wc * 32 + nj * 8 + grp;
                bfr2[nj][0] = f2tf(vt_s[(kb + tg) * FL_SV + ncol]);
                bfr2[nj][1] = f2tf(vt_s[(kb + tg + 4) * FL_SV + ncol]);
            }
#pragma unroll
            for (int mi = 0; mi < 2; mi++)
#pragma unroll
                for (int nj = 0; nj < 4; nj++)
                    mma_tf32(o[mi][nj], afr2[mi], bfr2[nj]);
        }
        __syncthreads();
        if (t + 2 < 8) load_pair(t + 2);
    }

    // ---- final sum combine + normalize + scrambled store ----
#pragma unroll
    for (int mi = 0; mi < 2; mi++)
#pragma unroll
        for (int hh = 0; hh < 2; hh++) {
            float v = s_run[mi][hh];
            v += __shfl_xor_sync(0xffffffffu, v, 1);
            v += __shfl_xor_sync(0xffffffffu, v, 2);
            s_red[wc][rowbase + mi * 16 + grp + hh * 8] = v;
        }
    __syncthreads();

    int bo = r & 3, ho = r >> 2;
    float* outp = g_attn_in + (size_t)(bo * Ss) * Dd + ho * 64;
#pragma unroll
    for (int mi = 0; mi < 2; mi++) {
        int lr0 = rowbase + mi * 16 + grp;
        float inv0 = 1.f / (s_red[0][lr0] + s_red[1][lr0]);
        float inv1 = 1.f / (s_red[0][lr0 + 8] + s_red[1][lr0 + 8]);
#pragma unroll
        for (int nj = 0; nj < 4; nj++) {
            int col = wc * 32 + nj * 8 + tg * 2;
            *(float2*)&outp[(size_t)(m0 + lr0) * Dd + col] =
                make_float2(o[mi][nj][0] * inv0, o[mi][nj][1] * inv0);
            *(float2*)&outp[(size_t)(m0 + lr0 + 8) * Dd + col] =
                make_float2(o[mi][nj][2] * inv1, o[mi][nj][3] * inv1);
        }
    }
}

// ---------------- mask conversion (robust to bool/int32/float32 layout) -----
__global__ void convert_mask_k(const unsigned char* __restrict__ raw) {
    int i = blockIdx.x * blockDim.x + threadIdx.x;
    if (i >= Mm) return;
    unsigned char v;
    if (raw[2] == 0x80 && raw[3] == 0x3F) {
        v = (((const float*)raw)[i] != 0.0f);
    } else if (raw[1] == 0) {
        v = (((const int*)raw)[i] != 0);
    } else {
        v = (raw[i] != 0);
    }
    g_maskc[i] = v;
}

// ---------------- reductions -------------------------------------------------
__device__ __forceinline__ float blockReduce(float v, float* sh, bool ismax) {
    __syncthreads();
#pragma unroll
    for (int o = 16; o > 0; o >>= 1) {
        float u = __shfl_xor_sync(0xffffffffu, v, o);
        v = ismax ? fmaxf(v, u) : (v + u);
    }
    int w = threadIdx.x >> 5;
    if ((threadIdx.x & 31) == 0) sh[w] = v;
    __syncthreads();
    if (threadIdx.x < 32) {
        float r = (threadIdx.x < 8) ? sh[threadIdx.x] : (ismax ? -INFINITY : 0.f);
#pragma unroll
        for (int o = 4; o > 0; o >>= 1) {
            float u = __shfl_xor_sync(0xffffffffu, r, o);
            r = ismax ? fmaxf(r, u) : (r + u);
        }
        if (threadIdx.x == 0) sh[0] = r;
    }
    __syncthreads();
    return sh[0];
}

// ---------------- add + layernorm + mask multiply ---------------------------
__global__ __launch_bounds__(256) void add_ln_mask_k(
    const float* __restrict__ x1, const float* __restrict__ x2,
    const float* __restrict__ gw, const float* __restrict__ bw,
    float* __restrict__ out)
{
    __shared__ float sh[32];
    int row = blockIdx.x;
    const float* p1 = x1 + (size_t)row * Dd;
    const float* p2 = x2 + (size_t)row * Dd;
    int tid = threadIdx.x;
    float4 a = *(const float4*)&p1[tid * 4];
    float4 c = *(const float4*)&p2[tid * 4];
    float v0 = a.x + c.x, v1 = a.y + c.y, v2 = a.z + c.z, v3 = a.w + c.w;
    float s  = blockReduce(v0 + v1 + v2 + v3, sh, false);
    float sq = blockReduce(v0*v0 + v1*v1 + v2*v2 + v3*v3, sh, false);
    float mean = s * (1.f / Dd);
    float var = sq * (1.f / Dd) - mean * mean;
    float inv = rsqrtf(var + 1e-3f);
    float mk = g_maskc[row] ? 1.f : 0.f;
    int c0 = tid * 4;
    float4 g4 = *(const float4*)&gw[c0];
    float4 b4 = *(const float4*)&bw[c0];
    float4 o;
    o.x = ((v0 - mean) * inv * g4.x + b4.x) * mk;
    o.y = ((v1 - mean) * inv * g4.y + b4.y) * mk;
    o.z = ((v2 - mean) * inv * g4.z + b4.z) * mk;
    o.w = ((v3 - mean) * inv * g4.w + b4.w) * mk;
    *(float4*)&out[(size_t)row * Dd + c0] = o;
}

// ---------------- launch -----------------------------------------------------
extern "C" void kernel_launch(void* const* d_in, const int* in_sizes, int n_in,
                              void* d_out, int out_size) {
    const float* dec_inp = (const float*)d_in[0];
    const unsigned char* mask = (const unsigned char*)d_in[1];
    const float* qkv_w  = (const float*)d_in[2];
    const float* qkv_b  = (const float*)d_in[3];
    const float* o_w    = (const float*)d_in[4];
    const float* ln1_g  = (const float*)d_in[5];
    const float* ln1_b  = (const float*)d_in[6];
    const float* conv1_w= (const float*)d_in[7];
    const float* conv1_b= (const float*)d_in[8];
    const float* conv2_w= (const float*)d_in[9];
    const float* conv2_b= (const float*)d_in[10];
    const float* ln2_g  = (const float*)d_in[11];
    const float* ln2_b  = (const float*)d_in[12];
    float* out = (float*)d_out;

    float* qkv;      cudaGetSymbolAddress((void**)&qkv, g_qkv);
    float* attn_in;  cudaGetSymbolAddress((void**)&attn_in, g_attn_in);
    float* attn_out; cudaGetSymbolAddress((void**)&attn_out, g_attn_out);
    float* out1;     cudaGetSymbolAddress((void**)&out1, g_out1);
    float* core;     cudaGetSymbolAddress((void**)&core, g_core);
    float* core2;    cudaGetSymbolAddress((void**)&core2, g_core2);

    cudaFuncSetAttribute(gemm_mma, cudaFuncAttributeMaxDynamicSharedMemorySize, SMEM_G256);
    cudaFuncSetAttribute(flash_k, cudaFuncAttributeMaxDynamicSharedMemorySize, SMEM_FLASH);

    convert_mask_k<<<(Mm + 255) / 256, 256>>>(mask);

    // QKV: [4096,1024] @ W[1024,3072] + b
    gemm_mma<<<dim3(3 * Dd / 256, Mm / 128, 1), 256, SMEM_G256>>>(
        dec_inp, qkv_w, qkv_b, qkv, Dd, Dd, 3 * Dd, 3 * Dd, 0, 0);
    // fused attention: scores + mask + softmax + PV, scrambled output
    flash_k<<<dim3(Ss / 128, 64), 256, SMEM_FLASH>>>(qkv);
    // O-proj: [4096,1024] @ W[1024,1024]
    gemm_mma<<<dim3(Dd / 256, Mm / 128, 1), 256, SMEM_G256>>>(
        attn_in, o_w, (const float*)nullptr, attn_out, Dd, Dd, Dd, Dd, 0, 0);
    add_ln_mask_k<<<Mm, 256>>>(dec_inp, attn_out, ln1_g, ln1_b, out1);
    // conv1 (implicit im2col): K=3*1024, N=4096, +bias, relu
    gemm_mma<<<dim3(DIi / 256, Mm / 128, 1), 256, SMEM_G256>>>(
        out1, conv1_w, conv1_b, core, 3 * Dd, 0, DIi, DIi, Dd, 1);
    // conv2: K=3*4096, N=1024, +bias
    gemm_mma<<<dim3(Dd / 256, Mm / 128, 1), 256, SMEM_G256>>>(
        core, conv2_w, conv2_b, core2, 3 * DIi, 0, Dd, Dd, DIi, 0);
    add_ln_mask_k<<<Mm, 256>>>(out1, core2, ln2_g, ln2_b, out);
}

// round 16
// speedup vs baseline: 1.0279x; 1.0279x over previous
#include <cuda_runtime.h>
#include <math.h>
#include <cstdint>

// Problem constants
#define Bb   4
#define Ss   1024
#define Dd   1024
#define DIi  4096
#define Mm   (Bb*Ss)      // 4096 rows

// ---------------- scratch (device globals; no allocations allowed) ----------
__device__ float g_qkv[(size_t)Mm * 3 * Dd];          // 4096 x 3072
__device__ float g_attn_in[(size_t)Mm * Dd];
__device__ float g_attn_out[(size_t)Mm * Dd];
__device__ float g_out1[(size_t)Mm * Dd];
__device__ float g_core[(size_t)Mm * DIi];
__device__ float g_core2[(size_t)Mm * Dd];
__device__ unsigned char g_maskc[Mm];

// ---------------- helpers ---------------------------------------------------
__device__ __forceinline__ uint32_t smem_u32(const void* p) {
    uint32_t a;
    asm("{ .reg .u64 t; cvta.to.shared.u64 t, %1; cvt.u32.u64 %0, t; }"
        : "=r"(a) : "l"(p));
    return a;
}
__device__ __forceinline__ void cp16(uint32_t dst, const void* src, int sz) {
    asm volatile("cp.async.ca.shared.global [%0], [%1], 16, %2;"
                 :: "r"(dst), "l"(src), "r"(sz));
}
__device__ __forceinline__ uint32_t f2tf(float x) {
    uint32_t r;
    asm("cvt.rna.tf32.f32 %0, %1;" : "=r"(r) : "f"(x));
    return r;
}
__device__ __forceinline__ void mma_tf32(float* c, const uint32_t* a, const uint32_t* b) {
    asm volatile(
        "mma.sync.aligned.m16n8k8.row.col.f32.tf32.tf32.f32 "
        "{%0,%1,%2,%3}, {%4,%5,%6,%7}, {%8,%9}, {%0,%1,%2,%3};"
        : "+f"(c[0]), "+f"(c[1]), "+f"(c[2]), "+f"(c[3])
        : "r"(a[0]), "r"(a[1]), "r"(a[2]), "r"(a[3]), "r"(b[0]), "r"(b[1]));
}

// ======================= mma.sync tf32 GEMM =================================
// R14: BM=128, BN=128, 128 threads (4 warps, 2x2 grid, warp tile 64x64 —
// same 1.0 LDS/MMA ratio as the proven R11 config), 2-stage cp.async.
// Regs ~180x128=23K, SMEM 71.7KB -> 2 CTAs/SM: 8 warps/SM in TWO independent
// barrier domains (one CTA's stalls covered by the other's MMAs).
// Raw fp32 bits feed tf32 MMA (HW truncation; R11-proven numerics).
// C[128x128] = A[128xK] @ W[K,N] row-major, fp32 accum, BK=32.
// convCin>0: A is im2col of X[B,S,Cin], ksize 3, SAME padding.
#define SA_  36
#define SB_  136            // 128 + 8
#define STG_A (128 * SA_)
#define STG_B (32 * SB_)
#define SMEM_GEMM (2 * (STG_A + STG_B) * 4)   // 71680

__global__ __launch_bounds__(128) void gemm_mma(
    const float* __restrict__ A, const float* __restrict__ Bw,
    const float* __restrict__ bias, float* __restrict__ C,
    int K, int lda, int ldb, int ldc, int convCin, int relu)
{
    extern __shared__ float sm[];
    float* As = sm;
    float* Bs = sm + 2 * STG_A;
    int tid = threadIdx.x;
    int m0 = blockIdx.y * 128, bn = blockIdx.x * 128;

    int NC = K >> 5;

    auto load_chunk = [&](int c, int stage) {
        int k0 = c << 5;
        float* sa = As + stage * STG_A;
        float* sb = Bs + stage * STG_B;
        if (convCin) {
            int t = k0 / convCin, cb2 = k0 - t * convCin;
#pragma unroll
            for (int i = 0; i < 8; i++) {
                int idx = tid + i * 128;          // 0..1023
                int row = idx >> 3, c4 = idx & 7;
                int m = m0 + row, b_ = m >> 10, s_ = m & 1023, ss = s_ + t - 1;
                const float* src = A + (size_t)(b_ * Ss + ss) * convCin + cb2 + c4 * 4;
                cp16(smem_u32(sa + row * SA_ + c4 * 4), src,
                     (ss >= 0 && ss < Ss) ? 16 : 0);
            }
        } else {
#pragma unroll
            for (int i = 0; i < 8; i++) {
                int idx = tid + i * 128;
                int row = idx >> 3, c4 = idx & 7;
                cp16(smem_u32(sa + row * SA_ + c4 * 4),
                     A + (size_t)(m0 + row) * lda + k0 + c4 * 4, 16);
            }
        }
#pragma unroll
        for (int i = 0; i < 8; i++) {
            int idx = tid + i * 128;              // 0..1023
            int kk = idx >> 5, n4 = idx & 31;
            cp16(smem_u32(sb + kk * SB_ + n4 * 4),
                 Bw + (size_t)(k0 + kk) * ldb + bn + n4 * 4, 16);
        }
        asm volatile("cp.async.commit_group;");
    };

    int w = tid >> 5, lane = tid & 31;
    int wr = w & 1, wc = w >> 1;      // 2x2 warp grid; warp tile 64x64
    int grp = lane >> 2, tg = lane & 3;

    float acc[4][8][4];
#pragma unroll
    for (int mi = 0; mi < 4; mi++)
#pragma unroll
        for (int nj = 0; nj < 8; nj++)
#pragma unroll
            for (int q = 0; q < 4; q++) acc[mi][nj][q] = 0.f;

    load_chunk(0, 0);
    for (int c = 0; c < NC; c++) {
        if (c + 1 < NC) {
            load_chunk(c + 1, (c + 1) & 1);
            asm volatile("cp.async.wait_group 1;");
        } else {
            asm volatile("cp.async.wait_group 0;");
        }
        __syncthreads();
        const uint32_t* sa = (const uint32_t*)(As + (c & 1) * STG_A);
        const uint32_t* sb = (const uint32_t*)(Bs + (c & 1) * STG_B);
#pragma unroll
        for (int ks = 0; ks < 4; ks++) {
            int kb = ks * 8;
            uint32_t afr[4][4];
#pragma unroll
            for (int mi = 0; mi < 4; mi++) {
                const uint32_t* ab = sa + (wr * 64 + mi * 16) * SA_ + kb;
                afr[mi][0] = ab[grp * SA_ + tg];
                afr[mi][1] = ab[(grp + 8) * SA_ + tg];
                afr[mi][2] = ab[grp * SA_ + tg + 4];
                afr[mi][3] = ab[(grp + 8) * SA_ + tg + 4];
            }
            uint32_t bfr[8][2];
#pragma unroll
            for (int nj = 0; nj < 8; nj++) {
                int ncol = wc * 64 + nj * 8 + grp;
                bfr[nj][0] = sb[(kb + tg) * SB_ + ncol];
                bfr[nj][1] = sb[(kb + tg + 4) * SB_ + ncol];
            }
#pragma unroll
            for (int mi = 0; mi < 4; mi++)
#pragma unroll
                for (int nj = 0; nj < 8; nj++)
                    mma_tf32(acc[mi][nj], afr[mi], bfr[nj]);
        }
        __syncthreads();
    }

#pragma unroll
    for (int mi = 0; mi < 4; mi++) {
        int r0 = m0 + wr * 64 + mi * 16 + grp;
#pragma unroll
        for (int nj = 0; nj < 8; nj++) {
            int c0 = bn + wc * 64 + nj * 8 + tg * 2;
            float v0 = acc[mi][nj][0], v1 = acc[mi][nj][1];
            float v2 = acc[mi][nj][2], v3 = acc[mi][nj][3];
            if (bias) {
                float b0 = bias[c0], b1 = bias[c0 + 1];
                v0 += b0; v1 += b1; v2 += b0; v3 += b1;
            }
            if (relu) {
                v0 = fmaxf(v0, 0.f); v1 = fmaxf(v1, 0.f);
                v2 = fmaxf(v2, 0.f); v3 = fmaxf(v3, 0.f);
            }
            *(float2*)&C[(size_t)r0 * ldc + c0] = make_float2(v0, v1);
            *(float2*)&C[(size_t)(r0 + 8) * ldc + c0] = make_float2(v2, v3);
        }
    }
}

// ======================= fused flash attention ==============================
// One block = (r = b*16+h, 128 q-rows). Loops over 8 key-tiles of 128.
// S = Q@K^T (tf32 mma), faithful mask (valid -> -1e30, pad -> s*0.125+1),
// online softmax (max/sum with cross-warp-pair exchange), O = P@V (tf32 mma).
// Output scramble: attn_in[bo= r%B][q][ (ho=r/B)*64 + d ].
#define FL_SK 68
#define FL_SV 72
#define FL_SP 132
#define SMEM_FLASH ((2*128*FL_SK + 2*128*FL_SV + 128*FL_SP) * 4)  // 210944

__global__ __launch_bounds__(256) void flash_k(const float* __restrict__ qkvp)
{
    extern __shared__ float sm[];
    float* Ks = sm;                               // 2 stages
    float* Vs = sm + 2 * 128 * FL_SK;             // 2 stages
    float* Ps = sm + 2 * 128 * FL_SK + 2 * 128 * FL_SV;  // P tile (also Q staging)
    __shared__ float s_red[2][128];
    __shared__ float s_mask[128];

    int tid = threadIdx.x;
    int r = blockIdx.y, m0 = blockIdx.x * 128;
    int bb = r >> 4, h = r & 15, mb = r & 3;
    const float* Qb = qkvp + (size_t)(bb * Ss) * 3072 + h * 64;
    const float* Kb = Qb + 1024;
    const float* Vb = Qb + 2048;

    int w = tid >> 5, lane = tid & 31;
    int wr = w & 3, wc = w >> 2;      // 4x2: warp = 32 q-rows x (64 keys | 32 dims)
    int grp = lane >> 2, tg = lane & 3;
    int rowbase = wr * 32;

    auto load_pair = [&](int t) {
        float* kd = Ks + (t & 1) * 128 * FL_SK;
        float* vd = Vs + (t & 1) * 128 * FL_SV;
        int j0 = t * 128;
#pragma unroll
        for (int i = 0; i < 8; i++) {
            int idx = tid + i * 256;              // 0..2047
            int row = idx >> 4, c4 = idx & 15;
            cp16(smem_u32(kd + row * FL_SK + c4 * 4),
                 Kb + (size_t)(j0 + row) * 3072 + c4 * 4, 16);
            cp16(smem_u32(vd + row * FL_SV + c4 * 4),
                 Vb + (size_t)(j0 + row) * 3072 + c4 * 4, 16);
        }
        asm volatile("cp.async.commit_group;");
    };
    load_pair(0);
    load_pair(1);

    // stage Q (128x64) into Ps area (stride FL_SK), then lift to registers
#pragma unroll
    for (int i = 0; i < 8; i++) {
        int idx = tid + i * 256;                  // float4 id 0..2047
        int row = idx >> 4, c4 = idx & 15;
        *(float4*)(Ps + row * FL_SK + c4 * 4) =
            *(const float4*)(Qb + (size_t)(m0 + row) * 3072 + c4 * 4);
    }
    __syncthreads();
    uint32_t qfr[2][8][4];
#pragma unroll
    for (int mi = 0; mi < 2; mi++) {
        const float* ab = Ps + (rowbase + mi * 16) * FL_SK;
#pragma unroll
        for (int ks = 0; ks < 8; ks++) {
            int kb = ks * 8;
            qfr[mi][ks][0] = f2tf(ab[grp * FL_SK + kb + tg]);
            qfr[mi][ks][1] = f2tf(ab[(grp + 8) * FL_SK + kb + tg]);
            qfr[mi][ks][2] = f2tf(ab[grp * FL_SK + kb + tg + 4]);
            qfr[mi][ks][3] = f2tf(ab[(grp + 8) * FL_SK + kb + tg + 4]);
        }
    }

    float o[2][4][4];
    float m_run[2][2], s_run[2][2];
#pragma unroll
    for (int mi = 0; mi < 2; mi++) {
        m_run[mi][0] = -INFINITY; m_run[mi][1] = -INFINITY;
        s_run[mi][0] = 0.f;       s_run[mi][1] = 0.f;
#pragma unroll
        for (int nj = 0; nj < 4; nj++)
#pragma unroll
            for (int q = 0; q < 4; q++) o[mi][nj][q] = 0.f;
    }

    for (int t = 0; t < 8; t++) {
        if (tid < 128)
            s_mask[tid] = g_maskc[mb * Ss + t * 128 + tid] ? 1.f : 0.f;
        if (t < 7) asm volatile("cp.async.wait_group 1;");
        else       asm volatile("cp.async.wait_group 0;");
        __syncthreads();
        const float* kt_s = Ks + (t & 1) * 128 * FL_SK;
        const float* vt_s = Vs + (t & 1) * 128 * FL_SV;

        // ---- S = Q @ K^T : warp computes 32 x 64 ----
        float s[2][8][4];
#pragma unroll
        for (int mi = 0; mi < 2; mi++)
#pragma unroll
            for (int nj = 0; nj < 8; nj++)
#pragma unroll
                for (int q = 0; q < 4; q++) s[mi][nj][q] = 0.f;
#pragma unroll
        for (int ks = 0; ks < 8; ks++) {
            int kb = ks * 8;
            uint32_t bfr[8][2];
#pragma unroll
            for (int nj = 0; nj < 8; nj++) {
                int ncol = wc * 64 + nj * 8 + grp;
                bfr[nj][0] = f2tf(kt_s[ncol * FL_SK + kb + tg]);
                bfr[nj][1] = f2tf(kt_s[ncol * FL_SK + kb + tg + 4]);
            }
#pragma unroll
            for (int mi = 0; mi < 2; mi++)
#pragma unroll
                for (int nj = 0; nj < 8; nj++)
                    mma_tf32(s[mi][nj], qfr[mi][ks], bfr[nj]);
        }

        // ---- faithful mask transform + tile row max ----
        float tmax[2][2];
        tmax[0][0] = tmax[0][1] = tmax[1][0] = tmax[1][1] = -INFINITY;
#pragma unroll
        for (int mi = 0; mi < 2; mi++)
#pragma unroll
            for (int nj = 0; nj < 8; nj++) {
                float mk0 = s_mask[wc * 64 + nj * 8 + tg * 2];
                float mk1 = s_mask[wc * 64 + nj * 8 + tg * 2 + 1];
                float v0 = (mk0 != 0.f) ? -1e30f : (s[mi][nj][0] * 0.125f + 1.0f);
                float v1 = (mk1 != 0.f) ? -1e30f : (s[mi][nj][1] * 0.125f + 1.0f);
                float v2 = (mk0 != 0.f) ? -1e30f : (s[mi][nj][2] * 0.125f + 1.0f);
                float v3 = (mk1 != 0.f) ? -1e30f : (s[mi][nj][3] * 0.125f + 1.0f);
                s[mi][nj][0] = v0; s[mi][nj][1] = v1;
                s[mi][nj][2] = v2; s[mi][nj][3] = v3;
                tmax[mi][0] = fmaxf(tmax[mi][0], fmaxf(v0, v1));
                tmax[mi][1] = fmaxf(tmax[mi][1], fmaxf(v2, v3));
            }
#pragma unroll
        for (int mi = 0; mi < 2; mi++)
#pragma unroll
            for (int hh = 0; hh < 2; hh++) {
                float v = tmax[mi][hh];
                v = fmaxf(v, __shfl_xor_sync(0xffffffffu, v, 1));
                v = fmaxf(v, __shfl_xor_sync(0xffffffffu, v, 2));
                tmax[mi][hh] = v;
                s_red[wc][rowbase + mi * 16 + grp + hh * 8] = v;
            }
        __syncthreads();

        float mnew[2][2];
#pragma unroll
        for (int mi = 0; mi < 2; mi++)
#pragma unroll
            for (int hh = 0; hh < 2; hh++) {
                float other = s_red[wc ^ 1][rowbase + mi * 16 + grp + hh * 8];
                float mn = fmaxf(m_run[mi][hh], fmaxf(tmax[mi][hh], other));
                float sc = __expf(m_run[mi][hh] - mn);
                s_run[mi][hh] *= sc;
                m_run[mi][hh] = mn;
                mnew[mi][hh] = mn;
#pragma unroll
                for (int nj = 0; nj < 4; nj++) {
                    o[mi][nj][hh * 2]     *= sc;
                    o[mi][nj][hh * 2 + 1] *= sc;
                }
            }

        // ---- P = exp(S - m), partial row sums, stage P to SMEM ----
#pragma unroll
        for (int mi = 0; mi < 2; mi++) {
            float ps0 = 0.f, ps1 = 0.f;
#pragma unroll
            for (int nj = 0; nj < 8; nj++) {
                float p0 = __expf(s[mi][nj][0] - mnew[mi][0]);
                float p1 = __expf(s[mi][nj][1] - mnew[mi][0]);
                float p2 = __expf(s[mi][nj][2] - mnew[mi][1]);
                float p3 = __expf(s[mi][nj][3] - mnew[mi][1]);
                ps0 += p0 + p1; ps1 += p2 + p3;
                int row = rowbase + mi * 16 + grp;
                int col = wc * 64 + nj * 8 + tg * 2;
                *(float2*)(Ps + row * FL_SP + col)       = make_float2(p0, p1);
                *(float2*)(Ps + (row + 8) * FL_SP + col) = make_float2(p2, p3);
            }
            s_run[mi][0] += ps0; s_run[mi][1] += ps1;
        }
        __syncthreads();

        // ---- O += P @ V : warp computes 32 x 32, k = 128 ----
#pragma unroll
        for (int ks2 = 0; ks2 < 16; ks2++) {
            int kb = ks2 * 8;
            uint32_t afr2[2][4];
#pragma unroll
            for (int mi = 0; mi < 2; mi++) {
                const float* ab = Ps + (rowbase + mi * 16) * FL_SP + kb;
                afr2[mi][0] = f2tf(ab[grp * FL_SP + tg]);
                afr2[mi][1] = f2tf(ab[(grp + 8) * FL_SP + tg]);
                afr2[mi][2] = f2tf(ab[grp * FL_SP + tg + 4]);
                afr2[mi][3] = f2tf(ab[(grp + 8) * FL_SP + tg + 4]);
            }
            uint32_t bfr2[4][2];
#pragma unroll
            for (int nj = 0; nj < 4; nj++) {
                int ncol = wc * 32 + nj * 8 + grp;
                bfr2[nj][0] = f2tf(vt_s[(kb + tg) * FL_SV + ncol]);
                bfr2[nj][1] = f2tf(vt_s[(kb + tg + 4) * FL_SV + ncol]);
            }
#pragma unroll
            for (int mi = 0; mi < 2; mi++)
#pragma unroll
                for (int nj = 0; nj < 4; nj++)
                    mma_tf32(o[mi][nj], afr2[mi], bfr2[nj]);
        }
        __syncthreads();
        if (t + 2 < 8) load_pair(t + 2);
    }

    // ---- final sum combine + normalize + scrambled store ----
#pragma unroll
    for (int mi = 0; mi < 2; mi++)
#pragma unroll
        for (int hh = 0; hh < 2; hh++) {
            float v = s_run[mi][hh];
            v += __shfl_xor_sync(0xffffffffu, v, 1);
            v += __shfl_xor_sync(0xffffffffu, v, 2);
            s_red[wc][rowbase + mi * 16 + grp + hh * 8] = v;
        }
    __syncthreads();

    int bo = r & 3, ho = r >> 2;
    float* outp = g_attn_in + (size_t)(bo * Ss) * Dd + ho * 64;
#pragma unroll
    for (int mi = 0; mi < 2; mi++) {
        int lr0 = rowbase + mi * 16 + grp;
        float inv0 = 1.f / (s_red[0][lr0] + s_red[1][lr0]);
        float inv1 = 1.f / (s_red[0][lr0 + 8] + s_red[1][lr0 + 8]);
#pragma unroll
        for (int nj = 0; nj < 4; nj++) {
            int col = wc * 32 + nj * 8 + tg * 2;
            *(float2*)&outp[(size_t)(m0 + lr0) * Dd + col] =
                make_float2(o[mi][nj][0] * inv0, o[mi][nj][1] * inv0);
            *(float2*)&outp[(size_t)(m0 + lr0 + 8) * Dd + col] =
                make_float2(o[mi][nj][2] * inv1, o[mi][nj][3] * inv1);
        }
    }
}

// ---------------- mask conversion (robust to bool/int32/float32 layout) -----
__global__ void convert_mask_k(const unsigned char* __restrict__ raw) {
    int i = blockIdx.x * blockDim.x + threadIdx.x;
    if (i >= Mm) return;
    unsigned char v;
    if (raw[2] == 0x80 && raw[3] == 0x3F) {
        v = (((const float*)raw)[i] != 0.0f);
    } else if (raw[1] == 0) {
        v = (((const int*)raw)[i] != 0);
    } else {
        v = (raw[i] != 0);
    }
    g_maskc[i] = v;
}

// ---------------- add + layernorm + mask multiply ---------------------------
// R14: single fused float2 reduction (sum, sumsq) — halves the sync rounds.
__global__ __launch_bounds__(256) void add_ln_mask_k(
    const float* __restrict__ x1, const float* __restrict__ x2,
    const float* __restrict__ gw, const float* __restrict__ bw,
    float* __restrict__ out)
{
    __shared__ float2 sh2[8];
    int row = blockIdx.x;
    const float* p1 = x1 + (size_t)row * Dd;
    const float* p2 = x2 + (size_t)row * Dd;
    int tid = threadIdx.x;
    float4 a = *(const float4*)&p1[tid * 4];
    float4 c = *(const float4*)&p2[tid * 4];
    float v0 = a.x + c.x, v1 = a.y + c.y, v2 = a.z + c.z, v3 = a.w + c.w;
    float2 r = make_float2(v0 + v1 + v2 + v3,
                           v0*v0 + v1*v1 + v2*v2 + v3*v3);
#pragma unroll
    for (int o = 16; o > 0; o >>= 1) {
        r.x += __shfl_xor_sync(0xffffffffu, r.x, o);
        r.y += __shfl_xor_sync(0xffffffffu, r.y, o);
    }
    if ((tid & 31) == 0) sh2[tid >> 5] = r;
    __syncthreads();
    if (tid < 32) {
        float2 t = (tid < 8) ? sh2[tid] : make_float2(0.f, 0.f);
#pragma unroll
        for (int o = 4; o > 0; o >>= 1) {
            t.x += __shfl_xor_sync(0xffffffffu, t.x, o);
            t.y += __shfl_xor_sync(0xffffffffu, t.y, o);
        }
        if (tid == 0) sh2[0] = t;
    }
    __syncthreads();
    float s = sh2[0].x, sq = sh2[0].y;
    float mean = s * (1.f / Dd);
    float var = sq * (1.f / Dd) - mean * mean;
    float inv = rsqrtf(var + 1e-3f);
    float mk = g_maskc[row] ? 1.f : 0.f;
    int c0 = tid * 4;
    float4 g4 = *(const float4*)&gw[c0];
    float4 b4 = *(const float4*)&bw[c0];
    float4 o;
    o.x = ((v0 - mean) * inv * g4.x + b4.x) * mk;
    o.y = ((v1 - mean) * inv * g4.y + b4.y) * mk;
    o.z = ((v2 - mean) * inv * g4.z + b4.z) * mk;
    o.w = ((v3 - mean) * inv * g4.w + b4.w) * mk;
    *(float4*)&out[(size_t)row * Dd + c0] = o;
}

// ---------------- launch -----------------------------------------------------
extern "C" void kernel_launch(void* const* d_in, const int* in_sizes, int n_in,
                              void* d_out, int out_size) {
    const float* dec_inp = (const float*)d_in[0];
    const unsigned char* mask = (const unsigned char*)d_in[1];
    const float* qkv_w  = (const float*)d_in[2];
    const float* qkv_b  = (const float*)d_in[3];
    const float* o_w    = (const float*)d_in[4];
    const float* ln1_g  = (const float*)d_in[5];
    const float* ln1_b  = (const float*)d_in[6];
    const float* conv1_w= (const float*)d_in[7];
    const float* conv1_b= (const float*)d_in[8];
    const float* conv2_w= (const float*)d_in[9];
    const float* conv2_b= (const float*)d_in[10];
    const float* ln2_g  = (const float*)d_in[11];
    const float* ln2_b  = (const float*)d_in[12];
    float* out = (float*)d_out;

    float* qkv;      cudaGetSymbolAddress((void**)&qkv, g_qkv);
    float* attn_in;  cudaGetSymbolAddress((void**)&attn_in, g_attn_in);
    float* attn_out; cudaGetSymbolAddress((void**)&attn_out, g_attn_out);
    float* out1;     cudaGetSymbolAddress((void**)&out1, g_out1);
    float* core;     cudaGetSymbolAddress((void**)&core, g_core);
    float* core2;    cudaGetSymbolAddress((void**)&core2, g_core2);

    cudaFuncSetAttribute(gemm_mma, cudaFuncAttributeMaxDynamicSharedMemorySize, SMEM_GEMM);
    cudaFuncSetAttribute(flash_k, cudaFuncAttributeMaxDynamicSharedMemorySize, SMEM_FLASH);

    convert_mask_k<<<(Mm + 255) / 256, 256>>>(mask);

    // QKV: [4096,1024] @ W[1024,3072] + b
    gemm_mma<<<dim3(3 * Dd / 128, Mm / 128, 1), 128, SMEM_GEMM>>>(
        dec_inp, qkv_w, qkv_b, qkv, Dd, Dd, 3 * Dd, 3 * Dd, 0, 0);
    // fused attention: scores + mask + softmax + PV, scrambled output
    flash_k<<<dim3(Ss / 128, 64), 256, SMEM_FLASH>>>(qkv);
    // O-proj: [4096,1024] @ W[1024,1024]
    gemm_mma<<<dim3(Dd / 128, Mm / 128, 1), 128, SMEM_GEMM>>>(
        attn_in, o_w, (const float*)nullptr, attn_out, Dd, Dd, Dd, Dd, 0, 0);
    add_ln_mask_k<<<Mm, 256>>>(dec_inp, attn_out, ln1_g, ln1_b, out1);
    // conv1 (implicit im2col): K=3*1024, N=4096, +bias, relu
    gemm_mma<<<dim3(DIi / 128, Mm / 128, 1), 128, SMEM_GEMM>>>(
        out1, conv1_w, conv1_b, core, 3 * Dd, 0, DIi, DIi, Dd, 1);
    // conv2: K=3*4096, N=1024, +bias
    gemm_mma<<<dim3(Dd / 128, Mm / 128, 1), 128, SMEM_GEMM>>>(
        core, conv2_w, conv2_b, core2, 3 * DIi, 0, Dd, Dd, DIi, 0);
    add_ln_mask_k<<<Mm, 256>>>(out1, core2, ln2_g, ln2_b, out);
}